// round 15
// baseline (speedup 1.0000x reference)
#include <cuda_runtime.h>
#include <cuda_fp16.h>
#include <stdint.h>

#define TPB        1024
#define CNT        8192
#define SPG        8192
#define HALF_PTS   4096                          // LDG path: [0,4096) ; TMA path: [4096,8192)
#define CHUNK_PTS  128
#define NCHUNK_H   (HALF_PTS / CHUNK_PTS)        // 32 TMA chunks per group
#define ROW_B      36
#define ARR_CHUNK_B (CHUNK_PTS * ROW_B)          // 4608 B per array per chunk
#define RAW_SLOT_B (2 * ARR_CHUNK_B)             // 9216 B per slot
#define NSLOT      3
#define BUF_B      (12 * CNT)                    // 98304 B per fp16 group buffer
#define RING_OFF   (2 * BUF_B)                   // 196608
#define MBAR_OFF   (RING_OFF + NSLOT * RAW_SLOT_B) // 224256
#define SMEM_BYTES (MBAR_OFF + 64)               // 224320 B (== R14, known-good size)

__device__ double g_acc = 0.0;
__device__ unsigned int g_count = 0;

__device__ __forceinline__ uint32_t smem_u32(const void* p) {
    return (uint32_t)__cvta_generic_to_shared(p);
}
__device__ __forceinline__ void mbar_init(uint32_t mbar, uint32_t cnt) {
    asm volatile("mbarrier.init.shared.b64 [%0], %1;" :: "r"(mbar), "r"(cnt) : "memory");
}
__device__ __forceinline__ void mbar_expect_tx(uint32_t mbar, uint32_t bytes) {
    asm volatile("mbarrier.arrive.expect_tx.shared.b64 _, [%0], %1;"
                 :: "r"(mbar), "r"(bytes) : "memory");
}
// contains bra.uni -> must ALWAYS be executed warp-convergent
__device__ __forceinline__ void mbar_wait(uint32_t mbar, uint32_t parity) {
    uint32_t done;
    asm volatile(
        "{\n\t.reg .pred p;\n\t"
        "mbarrier.try_wait.parity.acquire.cta.shared::cta.b64 p, [%1], %2;\n\t"
        "selp.b32 %0, 1, 0, p;\n\t}"
        : "=r"(done) : "r"(mbar), "r"(parity) : "memory");
    if (!done) {
        asm volatile(
            "{\n\t.reg .pred P1;\n\t"
            "W_%=:\n\t"
            "mbarrier.try_wait.parity.acquire.cta.shared::cta.b64 P1, [%0], %1, 0x989680;\n\t"
            "@P1 bra.uni D_%=;\n\t"
            "bra.uni W_%=;\n\t"
            "D_%=:\n\t}"
            :: "r"(mbar), "r"(parity) : "memory");
    }
}
__device__ __forceinline__ void bulk_copy(uint32_t dst, const void* src,
                                          uint32_t bytes, uint32_t mbar) {
    asm volatile(
        "cp.async.bulk.shared::cta.global.mbarrier::complete_tx::bytes [%0], [%1], %2, [%3];"
        :: "r"(dst), "l"(src), "r"(bytes), "r"(mbar) : "memory");
}
#define DMX_BAR() asm volatile("bar.sync 3, 256;" ::: "memory")   // demux team: warps 16..23

__device__ __forceinline__ float pair_term(int l, int r, const __half2* __restrict__ buf)
{
    float2 a  = __half22float2(buf[3 * l + 0]);   // in.xy
    float2 mz = __half22float2(buf[3 * l + 1]);   // (in.z, tg.z)
    float2 c  = __half22float2(buf[3 * l + 2]);   // tg.xy
    float2 b  = __half22float2(buf[3 * r + 0]);
    float2 nz = __half22float2(buf[3 * r + 1]);
    float2 d  = __half22float2(buf[3 * r + 2]);

    float ux = a.x - b.x, uy = a.y - b.y, uz = mz.x - nz.x;
    float d_in = sqrtf(fmaf(ux, ux, fmaf(uy, uy, uz * uz)));

    float vx = c.x - d.x, vy = c.y - d.y, vz = mz.y - nz.y;
    float d_tg = sqrtf(fmaf(vx, vx, fmaf(vy, vy, vz * vz)));

    float t = d_in - d_tg;
    return t * t;
}

__global__ void __launch_bounds__(TPB, 1)
rgn_hybrid_kernel(const float* __restrict__ inputs,
                  const float* __restrict__ target,
                  const int* __restrict__ left,
                  const int* __restrict__ right,
                  float* __restrict__ out,
                  int npairs, int ngroups)
{
    extern __shared__ unsigned char smem[];
    unsigned char* ring = smem + RING_OFF;
    const uint32_t ring_u32 = smem_u32(ring);
    const uint32_t mb = smem_u32(smem + MBAR_OFF);   // full[s] = mb + 8s

    const int K = (ngroups - blockIdx.x + gridDim.x - 1) / gridDim.x;
    const int total_chunks = K * NCHUNK_H;

    if (threadIdx.x == 0) {
        #pragma unroll
        for (int s = 0; s < NSLOT; s++) mbar_init(mb + 8 * s, 1);
    }
    __syncthreads();

    const int wid  = threadIdx.x >> 5;
    const int lane = threadIdx.x & 31;
    float acc = 0.0f;

    // ---- role-local helpers ----
    // TMA issue of chunk ic (back half of staged group m = ic/32)
    auto issue = [&](int ic) {
        const int m  = ic >> 5;
        const int ci = ic & (NCHUNK_H - 1);
        const int g  = blockIdx.x + m * gridDim.x;
        const int s  = ic % NSLOT;
        const size_t row0 = (size_t)(HALF_PTS + ci * CHUNK_PTS) * 9;
        const float* sin = inputs + (size_t)g * CNT * 9 + row0;
        const float* stg = target + (size_t)g * CNT * 9 + row0;
        const uint32_t slot = ring_u32 + (uint32_t)s * RAW_SLOT_B;
        mbar_expect_tx(mb + 8 * s, RAW_SLOT_B);
        bulk_copy(slot, sin, ARR_CHUNK_B, mb + 8 * s);
        bulk_copy(slot + ARR_CHUNK_B, stg, ARR_CHUNK_B, mb + 8 * s);
    };

    // LDG-stage front half of group g into bufb (producers: threadIdx.x in [0,512))
    auto stage_front = [&](int g, unsigned char* bufb) {
        const float* in_slab = inputs + (size_t)g * CNT * 9;
        const float* tg_slab = target + (size_t)g * CNT * 9;
        const int pt = threadIdx.x;
        #pragma unroll
        for (int k = 0; k < HALF_PTS / 512; k++) {   // 8 iters
            const int p = pt + k * 512;
            const float* ri = in_slab + (size_t)p * 9 + 3;
            const float* rt = tg_slab + (size_t)p * 9 + 3;
            float ix = __ldg(ri + 0), iy = __ldg(ri + 1), iz = __ldg(ri + 2);
            float tx = __ldg(rt + 0), ty = __ldg(rt + 1), tz = __ldg(rt + 2);
            *(__half2*)(bufb + 12 * p + 0) = __floats2half2_rn(ix, iy);
            *(__half2*)(bufb + 12 * p + 4) = __floats2half2_rn(iz, tz);
            *(__half2*)(bufb + 12 * p + 8) = __floats2half2_rn(tx, ty);
        }
    };

    // demux the back half of staged group m into bufb (demux team: tt in [0,256))
    auto demux_half = [&](int m, unsigned char* bufb) {
        const int tt = threadIdx.x - 512;
        for (int ci = 0; ci < NCHUNK_H; ci++) {
            const int ic = m * NCHUNK_H + ci;
            const int s  = ic % NSLOT;
            mbar_wait(mb + 8 * s, (uint32_t)((ic / NSLOT) & 1));   // 8 warps, convergent

            const unsigned char* slot = ring + (size_t)s * RAW_SLOT_B;
            if (tt < CHUNK_PTS) {
                const float* r = (const float*)(slot + 36 * tt + 12);          // inputs row
                const int p = HALF_PTS + ci * CHUNK_PTS + tt;
                *(__half2*)(bufb + 12 * p)     = __floats2half2_rn(r[0], r[1]);
                *(__half*) (bufb + 12 * p + 4) = __float2half_rn(r[2]);
            } else {
                const int q = tt - CHUNK_PTS;
                const float* r = (const float*)(slot + ARR_CHUNK_B + 36 * q + 12); // target row
                const int p = HALF_PTS + ci * CHUNK_PTS + q;
                *(__half*) (bufb + 12 * p + 6) = __float2half_rn(r[2]);
                *(__half2*)(bufb + 12 * p + 8) = __floats2half2_rn(r[0], r[1]);
            }
            DMX_BAR();   // team reads of slot s done -> safe to reissue
            if (tt == 0 && ic + NSLOT < total_chunks) issue(ic + NSLOT);
        }
    };

    // ================= prologue: stage group 0 into buf[0] =================
    if (wid < 16) {
        stage_front(blockIdx.x, smem);
    } else if (wid < 24) {
        if (threadIdx.x == 512) {
            #pragma unroll
            for (int k = 0; k < NSLOT; k++) if (k < total_chunks) issue(k);
        }
        demux_half(0, smem);
    }
    // consumers idle in prologue
    __syncthreads();

    // ================= main rounds =================
    for (int r = 0; r < K; r++) {
        const int nb = (r + 1) & 1;
        unsigned char* nbuf = smem + (size_t)nb * BUF_B;

        if (r + 1 < K) {
            if (wid < 16) {
                stage_front(blockIdx.x + (r + 1) * gridDim.x, nbuf);
            } else if (wid < 24) {
                demux_half(r + 1, nbuf);
            }
        }
        if (wid >= 24) {
            const __half2* buf = (const __half2*)(smem + (size_t)(r & 1) * BUF_B);
            const int g = blockIdx.x + r * gridDim.x;
            const int4* Lg = (const int4*)(left  + (size_t)g * SPG);
            const int4* Rg = (const int4*)(right + (size_t)g * SPG);
            const int ct = threadIdx.x - 768;   // 0..255
            #pragma unroll
            for (int j = 0; j < SPG / (4 * 256); j++) {   // 8 iters, 4 pairs each
                const int i = ct + j * 256;
                int4 L = __ldg(Lg + i);
                int4 R = __ldg(Rg + i);
                acc += pair_term(L.x & (CNT - 1), R.x & (CNT - 1), buf);
                acc += pair_term(L.y & (CNT - 1), R.y & (CNT - 1), buf);
                acc += pair_term(L.z & (CNT - 1), R.z & (CNT - 1), buf);
                acc += pair_term(L.w & (CNT - 1), R.w & (CNT - 1), buf);
            }
        }
        __syncthreads();   // outside all role branches: all 1024 threads arrive
    }

    // block reduce (only consumer warps carry nonzero acc)
    #pragma unroll
    for (int off = 16; off > 0; off >>= 1)
        acc += __shfl_down_sync(0xFFFFFFFFu, acc, off);

    __shared__ float warp_sums[TPB / 32];
    if (lane == 0) warp_sums[wid] = acc;
    __syncthreads();

    if (wid == 0) {
        float s = (lane < TPB / 32) ? warp_sums[lane] : 0.0f;
        #pragma unroll
        for (int off = 16; off > 0; off >>= 1)
            s += __shfl_down_sync(0xFFFFFFFFu, s, off);

        if (lane == 0) {
            atomicAdd(&g_acc, (double)s);
            __threadfence();
            unsigned int done = atomicAdd(&g_count, 1u);
            if (done == gridDim.x - 1) {
                out[0] = (float)(g_acc / (double)npairs);
                g_acc = 0.0;     // reset for next graph replay
                g_count = 0;
            }
        }
    }
}

extern "C" void kernel_launch(void* const* d_in, const int* in_sizes, int n_in,
                              void* d_out, int out_size) {
    const float* inputs = (const float*)d_in[0];
    const float* target = (const float*)d_in[1];
    const int*   left   = (const int*)d_in[2];
    const int*   right  = (const int*)d_in[3];
    float* out = (float*)d_out;

    int npairs  = in_sizes[2];
    int ngroups = npairs / SPG;   // 512

    static int num_sms = 0;
    if (num_sms == 0) {
        cudaDeviceProp prop;
        cudaGetDeviceProperties(&prop, 0);
        num_sms = prop.multiProcessorCount;   // 152 on GB300
    }
    int grid = (num_sms < ngroups) ? num_sms : ngroups;

    cudaFuncSetAttribute(rgn_hybrid_kernel,
                         cudaFuncAttributeMaxDynamicSharedMemorySize, SMEM_BYTES);

    rgn_hybrid_kernel<<<grid, TPB, SMEM_BYTES>>>(inputs, target, left, right,
                                                 out, npairs, ngroups);
}

// round 17
// speedup vs baseline: 1.4623x; 1.4623x over previous
#include <cuda_runtime.h>
#include <cuda_fp16.h>
#include <math.h>

#define TPB    1024
#define HALF_T 512               // steady-state: producers [512,1024), consumers [0,512)
#define CNT    8192              // points per group
#define SPG    8192              // pairs per group
#define BUF_H2 (3 * CNT)         // half2 slots per buffer (12 B/point) = 96 KB
#define SMEM_BYTES (2 * BUF_H2 * 4)   // 192 KB double buffer

__device__ double g_acc = 0.0;
__device__ unsigned int g_count = 0;

// Interleaved layout per point p:
//   buf[3p+0] = (in.x, in.y)   buf[3p+1] = (in.z, tg.z)   buf[3p+2] = (tg.x, tg.y)
__device__ __forceinline__ void stage_group(const float* __restrict__ inputs,
                                            const float* __restrict__ target,
                                            int g, __half2* __restrict__ buf,
                                            int pt, int nstage)   // thread pt of nstage
{
    const float* in_slab = inputs + (size_t)g * CNT * 9;
    const float* tg_slab = target + (size_t)g * CNT * 9;
    #pragma unroll 4
    for (int p = pt; p < CNT; p += nstage) {
        const float* ri = in_slab + (size_t)p * 9 + 3;
        const float* rt = tg_slab + (size_t)p * 9 + 3;
        float ix = __ldg(ri + 0), iy = __ldg(ri + 1), iz = __ldg(ri + 2);
        float tx = __ldg(rt + 0), ty = __ldg(rt + 1), tz = __ldg(rt + 2);
        buf[3 * p + 0] = __floats2half2_rn(ix, iy);
        buf[3 * p + 1] = __floats2half2_rn(iz, tz);
        buf[3 * p + 2] = __floats2half2_rn(tx, ty);
    }
}

__device__ __forceinline__ float pair_term(int l, int r, const __half2* __restrict__ buf)
{
    float2 a  = __half22float2(buf[3 * l + 0]);
    float2 mz = __half22float2(buf[3 * l + 1]);
    float2 c  = __half22float2(buf[3 * l + 2]);
    float2 b  = __half22float2(buf[3 * r + 0]);
    float2 nz = __half22float2(buf[3 * r + 1]);
    float2 d  = __half22float2(buf[3 * r + 2]);

    float ux = a.x - b.x, uy = a.y - b.y, uz = mz.x - nz.x;
    float d_in = sqrtf(fmaf(ux, ux, fmaf(uy, uy, uz * uz)));

    float vx = c.x - d.x, vy = c.y - d.y, vz = mz.y - nz.y;
    float d_tg = sqrtf(fmaf(vx, vx, fmaf(vy, vy, vz * vz)));

    float t = d_in - d_tg;
    return t * t;
}

__device__ __forceinline__ float consume_group(const int* __restrict__ left,
                                               const int* __restrict__ right,
                                               int g, const __half2* __restrict__ buf,
                                               int ct, int ncons)   // thread ct of ncons
{
    const int4* Lg = (const int4*)(left  + (size_t)g * SPG);
    const int4* Rg = (const int4*)(right + (size_t)g * SPG);
    float acc = 0.0f;
    for (int i = ct; i < SPG / 4; i += ncons) {
        int4 L = __ldg(Lg + i);
        int4 R = __ldg(Rg + i);
        acc += pair_term(L.x & (CNT - 1), R.x & (CNT - 1), buf);
        acc += pair_term(L.y & (CNT - 1), R.y & (CNT - 1), buf);
        acc += pair_term(L.z & (CNT - 1), R.z & (CNT - 1), buf);
        acc += pair_term(L.w & (CNT - 1), R.w & (CNT - 1), buf);
    }
    return acc;
}

__global__ void __launch_bounds__(TPB, 1)
rgn_ws2_kernel(const float* __restrict__ inputs,
               const float* __restrict__ target,
               const int* __restrict__ left,
               const int* __restrict__ right,
               float* __restrict__ out,
               int npairs, int ngroups)
{
    extern __shared__ unsigned char smem_raw[];
    __half2* buf0 = (__half2*)smem_raw;
    __half2* buf1 = buf0 + BUF_H2;

    const bool is_prod = (threadIdx.x >= HALF_T);
    const int  role_t  = is_prod ? (threadIdx.x - HALF_T) : threadIdx.x;

    // groups for this CTA: blockIdx.x + r*gridDim.x, r = 0..K-1
    const int K = (ngroups - blockIdx.x + gridDim.x - 1) / gridDim.x;

    float acc = 0.0f;
    for (int r = 0; r <= K; r++) {
        __syncthreads();   // uniform: all 1024 threads, every round

        __half2* sbuf = (r & 1) ? buf1 : buf0;              // stage target
        const __half2* cbuf = ((r - 1) & 1) ? buf1 : buf0;  // consume source

        if (r == 0) {
            // prologue: ALL threads stage group 0 (nothing to consume yet)
            stage_group(inputs, target, blockIdx.x, sbuf, threadIdx.x, TPB);
        } else if (r == K) {
            // epilogue: ALL threads consume the last group (nothing to stage)
            acc += consume_group(left, right, blockIdx.x + (r - 1) * gridDim.x,
                                 cbuf, threadIdx.x, TPB);
        } else {
            if (is_prod) {
                stage_group(inputs, target, blockIdx.x + r * gridDim.x,
                            sbuf, role_t, HALF_T);
            } else {
                acc += consume_group(left, right, blockIdx.x + (r - 1) * gridDim.x,
                                     cbuf, role_t, HALF_T);
            }
        }
    }
    __syncthreads();

    // block reduce
    #pragma unroll
    for (int off = 16; off > 0; off >>= 1)
        acc += __shfl_down_sync(0xFFFFFFFFu, acc, off);

    __shared__ float warp_sums[TPB / 32];
    const int lane = threadIdx.x & 31;
    const int wid  = threadIdx.x >> 5;
    if (lane == 0) warp_sums[wid] = acc;
    __syncthreads();

    if (wid == 0) {
        float s = (lane < TPB / 32) ? warp_sums[lane] : 0.0f;
        #pragma unroll
        for (int off = 16; off > 0; off >>= 1)
            s += __shfl_down_sync(0xFFFFFFFFu, s, off);

        if (lane == 0) {
            atomicAdd(&g_acc, (double)s);
            __threadfence();
            unsigned int done = atomicAdd(&g_count, 1u);
            if (done == gridDim.x - 1) {
                out[0] = (float)(g_acc / (double)npairs);
                g_acc = 0.0;     // reset for next graph replay
                g_count = 0;
            }
        }
    }
}

extern "C" void kernel_launch(void* const* d_in, const int* in_sizes, int n_in,
                              void* d_out, int out_size) {
    const float* inputs = (const float*)d_in[0];
    const float* target = (const float*)d_in[1];
    const int*   left   = (const int*)d_in[2];
    const int*   right  = (const int*)d_in[3];
    float* out = (float*)d_out;

    int npairs  = in_sizes[2];
    int ngroups = npairs / SPG;   // 512

    static int num_sms = 0;
    if (num_sms == 0) {
        cudaDeviceProp prop;
        cudaGetDeviceProperties(&prop, 0);
        num_sms = prop.multiProcessorCount;   // 152 on GB300
    }
    int grid = (num_sms < ngroups) ? num_sms : ngroups;

    cudaFuncSetAttribute(rgn_ws2_kernel,
                         cudaFuncAttributeMaxDynamicSharedMemorySize, SMEM_BYTES);

    rgn_ws2_kernel<<<grid, TPB, SMEM_BYTES>>>(inputs, target, left, right,
                                              out, npairs, ngroups);
}